// round 4
// baseline (speedup 1.0000x reference)
#include <cuda_runtime.h>

#define BATCH 4096
#define FEAT  512
#define NUMC  10000

#define BLOCK_THREADS 256
#define WARPS_PER_BLOCK (BLOCK_THREADS / 32)        // 8
#define GRID_BLOCKS (BATCH / WARPS_PER_BLOCK)       // 512

// Scratch (no cudaMalloc allowed)
__device__ float g_bsum[GRID_BLOCKS];

// ---------------------------------------------------------------------------
// Kernel 1: per-warp squared distance to the gathered center row, clipped,
// reduced to ONE float per block. No fences/atomics/tail -> grid drains fast.
// ---------------------------------------------------------------------------
__global__ void __launch_bounds__(BLOCK_THREADS)
dist_kernel(const float* __restrict__ x,
            const int*   __restrict__ labels32,
            const float* __restrict__ centers) {
    const int lane = threadIdx.x & 31;
    const int wid  = threadIdx.x >> 5;
    const int row  = blockIdx.x * WARPS_PER_BLOCK + wid;

    // dtype probe: odd words of first 64 int32 all zero <=> int64 labels.
    // P(false positive for int32 labels) = 1e-128. Same fixed probe every warp.
    int probe = __ldg(&labels32[2 * lane + 1]);
    int labA  = __ldg(&labels32[2 * row]);    // int64 candidate (low word)
    int labB  = __ldg(&labels32[row]);        // int32 candidate

    const float4* xr = reinterpret_cast<const float4*>(x + (size_t)row * FEAT);
    float4 xv[4];
#pragma unroll
    for (int i = 0; i < 4; i++) xv[i] = __ldg(&xr[lane + 32 * i]);

    bool is64 = (__ballot_sync(0xffffffffu, probe != 0) == 0u);
    int  lab  = is64 ? labA : labB;

    const float4* cr = reinterpret_cast<const float4*>(centers + (size_t)lab * FEAT);

    float a0 = 0.f, a1 = 0.f, a2 = 0.f, a3 = 0.f;
#pragma unroll
    for (int i = 0; i < 4; i++) {
        float4 cv = __ldg(&cr[lane + 32 * i]);
        float d0 = xv[i].x - cv.x;
        float d1 = xv[i].y - cv.y;
        float d2 = xv[i].z - cv.z;
        float d3 = xv[i].w - cv.w;
        a0 = fmaf(d0, d0, a0);
        a1 = fmaf(d1, d1, a1);
        a2 = fmaf(d2, d2, a2);
        a3 = fmaf(d3, d3, a3);
    }
    float acc = (a0 + a1) + (a2 + a3);
#pragma unroll
    for (int o = 16; o > 0; o >>= 1)
        acc += __shfl_xor_sync(0xffffffffu, acc, o);

    __shared__ float sh[WARPS_PER_BLOCK];
    if (lane == 0)
        sh[wid] = fminf(fmaxf(acc, 1e-12f), 1e12f);   // clip diagonal entry
    __syncthreads();

    if (threadIdx.x == 0) {
        // fixed-order deterministic block sum (8 values)
        float s = 0.0f;
#pragma unroll
        for (int w = 0; w < WARPS_PER_BLOCK; w++) s += sh[w];
        g_bsum[blockIdx.x] = s;
    }
}

// ---------------------------------------------------------------------------
// Kernel 2: deterministic fixed-order reduction of 512 block sums -> loss.
// ---------------------------------------------------------------------------
__global__ void __launch_bounds__(512)
reduce_kernel(float* __restrict__ out) {
    __shared__ float sh[16];
    const int t = threadIdx.x;

    float s = g_bsum[t];
#pragma unroll
    for (int o = 16; o > 0; o >>= 1)
        s += __shfl_xor_sync(0xffffffffu, s, o);
    if ((t & 31) == 0) sh[t >> 5] = s;
    __syncthreads();
    if (t == 0) {
        float tot = 0.0f;
#pragma unroll
        for (int w = 0; w < 16; w++) tot += sh[w];
        float base = (float)((double)(NUMC - 1) * 1e-12);  // clipped masked zeros
        out[0] = tot / (float)BATCH + base;
    }
}

extern "C" void kernel_launch(void* const* d_in, const int* in_sizes, int n_in,
                              void* d_out, int out_size) {
    const float* x       = (const float*)d_in[0];
    const int*   labels  = (const int*)  d_in[1];
    const float* centers = (const float*)d_in[2];
    float*       out     = (float*)d_out;

    dist_kernel<<<GRID_BLOCKS, BLOCK_THREADS>>>(x, labels, centers);
    reduce_kernel<<<1, 512>>>(out);
}